// round 3
// baseline (speedup 1.0000x reference)
#include <cuda_runtime.h>
#include <math.h>

#define N_NODES 50000
#define D 128
#define EPS 1e-5f

// -------- scratch (allocation-free: __device__ globals) --------
__device__ float g_h[N_NODES * D];      // pre/post-BN hidden
__device__ float g_agg[N_NODES * D];    // edge num, then agg (in place)
__device__ float g_rst[N_NODES * D];    // relu(GEMM2) output
__device__ float g_den[N_NODES];
__device__ float g_sum1[D], g_sq1[D], g_sum2[D], g_sq2[D];
__device__ float g_a1[D], g_b1[D], g_a2[D], g_b2[D];

// -------- zero the accumulated scratch every launch (graph replay!) --------
__global__ void zero_kernel() {
    int idx = blockIdx.x * blockDim.x + threadIdx.x;
    int tot = blockDim.x * gridDim.x;
    float4 z = make_float4(0.f, 0.f, 0.f, 0.f);
    for (int i = idx; i < N_NODES * D / 4; i += tot) ((float4*)g_agg)[i] = z;
    for (int i = idx; i < N_NODES; i += tot) g_den[i] = 0.f;
    if (idx < D) { g_sum1[idx] = 0.f; g_sq1[idx] = 0.f; g_sum2[idx] = 0.f; g_sq2[idx] = 0.f; }
}

// -------- tiled SIMT fp32 GEMM: C = relu(A_concat @ B^T + bias), fused col stats --------
// BM=64 rows, BN=128 cols (full width), BK=32. 256 threads, each 8x4 outputs.
// PHASE 0: A=feat (K=128), C=g_h, stats -> g_sum1/g_sq1
// PHASE 1: A=feat for k<128 else g_agg (K=256), C=g_rst, stats -> g_sum2/g_sq2
template <int K, int PHASE>
__global__ __launch_bounds__(256) void gemm_relu_stats(
    const float* __restrict__ A, const float* __restrict__ B,
    const float* __restrict__ bias)
{
    __shared__ float As[32][64];
    __shared__ float Bs[32][128];
    __shared__ float s_sum[128];
    __shared__ float s_sq[128];

    const int tid = threadIdx.x;
    const int r0 = blockIdx.x * 64;
    const int tcol = tid & 31;   // cols 4*tcol .. 4*tcol+3
    const int trow = tid >> 5;   // rows 8*trow .. 8*trow+7

    float acc[8][4];
#pragma unroll
    for (int r = 0; r < 8; r++)
#pragma unroll
        for (int c = 0; c < 4; c++) acc[r][c] = 0.f;

    for (int k0 = 0; k0 < K; k0 += 32) {
        const float* Asrc = (PHASE == 1 && k0 >= 128) ? g_agg : A;
        const int kbase = (PHASE == 1 && k0 >= 128) ? (k0 - 128) : k0;

        // A tile: 64 rows x 32 k -> As[k][row]. 512 float4 loads, 2/thread.
#pragma unroll
        for (int i = 0; i < 2; i++) {
            int idx = tid + i * 256;
            int row = idx & 63;
            int kk4 = (idx >> 6) << 2;
            int grow = r0 + row;
            float4 v = make_float4(0.f, 0.f, 0.f, 0.f);
            if (grow < N_NODES)
                v = *(const float4*)(Asrc + (size_t)grow * 128 + kbase + kk4);
            As[kk4 + 0][row] = v.x; As[kk4 + 1][row] = v.y;
            As[kk4 + 2][row] = v.z; As[kk4 + 3][row] = v.w;
        }
        // B tile: 128 j x 32 k -> Bs[k][j]. 1024 float4 loads, 4/thread.
#pragma unroll
        for (int i = 0; i < 4; i++) {
            int idx = tid + i * 256;
            int j = idx & 127;
            int kk4 = (idx >> 7) << 2;
            float4 v = *(const float4*)(B + (size_t)j * K + k0 + kk4);
            Bs[kk4 + 0][j] = v.x; Bs[kk4 + 1][j] = v.y;
            Bs[kk4 + 2][j] = v.z; Bs[kk4 + 3][j] = v.w;
        }
        __syncthreads();

#pragma unroll
        for (int kk = 0; kk < 32; kk++) {
            float4 b4 = *(const float4*)&Bs[kk][tcol * 4];
            float4 a0 = *(const float4*)&As[kk][trow * 8];
            float4 a1 = *(const float4*)&As[kk][trow * 8 + 4];
            float ar[8] = {a0.x, a0.y, a0.z, a0.w, a1.x, a1.y, a1.z, a1.w};
            float bc[4] = {b4.x, b4.y, b4.z, b4.w};
#pragma unroll
            for (int r = 0; r < 8; r++)
#pragma unroll
                for (int c = 0; c < 4; c++) acc[r][c] += ar[r] * bc[c];
        }
        __syncthreads();
    }

    // epilogue: bias + relu + store + column stats
    if (tid < 128) { s_sum[tid] = 0.f; s_sq[tid] = 0.f; }
    __syncthreads();

    float bsv[4];
#pragma unroll
    for (int c = 0; c < 4; c++) bsv[c] = bias[tcol * 4 + c];

    float* Cout = (PHASE == 0) ? g_h : g_rst;
    float ps[4] = {0.f, 0.f, 0.f, 0.f};
    float pq[4] = {0.f, 0.f, 0.f, 0.f};
#pragma unroll
    for (int r = 0; r < 8; r++) {
        int grow = r0 + trow * 8 + r;
        if (grow < N_NODES) {
            float4 v;
            float vv[4];
#pragma unroll
            for (int c = 0; c < 4; c++) {
                float x = acc[r][c] + bsv[c];
                x = fmaxf(x, 0.f);
                vv[c] = x;
                ps[c] += x;
                pq[c] += x * x;
            }
            v.x = vv[0]; v.y = vv[1]; v.z = vv[2]; v.w = vv[3];
            *(float4*)(Cout + (size_t)grow * 128 + tcol * 4) = v;
        }
    }
#pragma unroll
    for (int c = 0; c < 4; c++) {
        atomicAdd(&s_sum[tcol * 4 + c], ps[c]);
        atomicAdd(&s_sq[tcol * 4 + c], pq[c]);
    }
    __syncthreads();
    if (tid < 128) {
        float* gsum = (PHASE == 0) ? g_sum1 : g_sum2;
        float* gsq  = (PHASE == 0) ? g_sq1  : g_sq2;
        atomicAdd(&gsum[tid], s_sum[tid]);
        atomicAdd(&gsq[tid], s_sq[tid]);
    }
}

// -------- BN params: a = gamma*rstd, b = beta - mean*a --------
__global__ void bn_params(int phase, const float* __restrict__ gamma,
                          const float* __restrict__ beta) {
    int c = threadIdx.x;
    const float* sum = phase ? g_sum2 : g_sum1;
    const float* sq  = phase ? g_sq2  : g_sq1;
    float* pa = phase ? g_a2 : g_a1;
    float* pb = phase ? g_b2 : g_b1;
    float mean = sum[c] * (1.f / N_NODES);
    float var = sq[c] * (1.f / N_NODES) - mean * mean;
    float rstd = rsqrtf(var + EPS);
    float a = gamma[c] * rstd;
    pa[c] = a;
    pb[c] = beta[c] - mean * a;
}

// -------- apply BN1 to g_h in place --------
__global__ void apply_bn1() {
    int idx = blockIdx.x * blockDim.x + threadIdx.x;
    if (idx >= N_NODES * 32) return;
    int c4 = idx & 31;
    float4 a = ((const float4*)g_a1)[c4];
    float4 b = ((const float4*)g_b1)[c4];
    float4 v = ((float4*)g_h)[idx];
    v.x = v.x * a.x + b.x; v.y = v.y * a.y + b.y;
    v.z = v.z * a.z + b.z; v.w = v.w * a.w + b.w;
    ((float4*)g_h)[idx] = v;
}

// -------- edge scatter: warp per edge, atomics into g_agg(num) + g_den --------
__global__ void edge_kernel(const float* __restrict__ w, const int* __restrict__ src,
                            const int* __restrict__ dst, int E) {
    int gw = (blockIdx.x * blockDim.x + threadIdx.x) >> 5;
    int lane = threadIdx.x & 31;
    if (gw >= E) return;
    int s = src[gw], d = dst[gw];
    float we = w[gw];
    float4 hv = ((const float4*)g_h)[(size_t)s * 32 + lane];
    float* np = g_agg + (size_t)d * 128 + lane * 4;
    atomicAdd(np + 0, we * hv.x);
    atomicAdd(np + 1, we * hv.y);
    atomicAdd(np + 2, we * hv.z);
    atomicAdd(np + 3, we * hv.w);
    if (lane == 0) atomicAdd(&g_den[d], we);
}

// -------- agg = den!=0 ? num/den : h   (in place in g_agg) --------
__global__ void agg_kernel() {
    int idx = blockIdx.x * blockDim.x + threadIdx.x;
    if (idx >= N_NODES * 32) return;
    int n = idx >> 5;
    float den = g_den[n];
    float4 v;
    if (den != 0.f) {
        float inv = 1.f / den;
        v = ((const float4*)g_agg)[idx];
        v.x *= inv; v.y *= inv; v.z *= inv; v.w *= inv;
    } else {
        v = ((const float4*)g_h)[idx];
    }
    ((float4*)g_agg)[idx] = v;
}

// -------- BN2 + row L2 normalize: warp per row --------
__global__ void final_kernel(float* __restrict__ out) {
    int gw = (blockIdx.x * blockDim.x + threadIdx.x) >> 5;
    int lane = threadIdx.x & 31;
    if (gw >= N_NODES) return;
    float4 a = ((const float4*)g_a2)[lane];
    float4 b = ((const float4*)g_b2)[lane];
    float4 v = ((const float4*)g_rst)[(size_t)gw * 32 + lane];
    v.x = v.x * a.x + b.x; v.y = v.y * a.y + b.y;
    v.z = v.z * a.z + b.z; v.w = v.w * a.w + b.w;
    float ss = v.x * v.x + v.y * v.y + v.z * v.z + v.w * v.w;
#pragma unroll
    for (int o = 16; o > 0; o >>= 1) ss += __shfl_xor_sync(0xFFFFFFFFu, ss, o);
    float norm = sqrtf(ss);
    float inv = (norm == 0.f) ? 1.f : 1.f / norm;
    v.x *= inv; v.y *= inv; v.z *= inv; v.w *= inv;
    ((float4*)out)[(size_t)gw * 32 + lane] = v;
}

extern "C" void kernel_launch(void* const* d_in, const int* in_sizes, int n_in,
                              void* d_out, int out_size) {
    const float* feat  = (const float*)d_in[0];
    const float* w     = (const float*)d_in[1];
    const float* Qw    = (const float*)d_in[2];
    const float* Qb    = (const float*)d_in[3];
    const float* Ww    = (const float*)d_in[4];
    const float* Wb    = (const float*)d_in[5];
    const float* gamma = (const float*)d_in[6];
    const float* beta  = (const float*)d_in[7];
    const int* src     = (const int*)d_in[8];
    const int* dst     = (const int*)d_in[9];
    const int E = in_sizes[1];
    float* out = (float*)d_out;

    const int gemm_grid = (N_NODES + 63) / 64;   // 782
    const int ew_grid = (N_NODES * 32 + 255) / 256;  // 6250

    zero_kernel<<<1024, 256>>>();
    gemm_relu_stats<128, 0><<<gemm_grid, 256>>>(feat, Qw, Qb);
    bn_params<<<1, 128>>>(0, gamma, beta);
    apply_bn1<<<ew_grid, 256>>>();
    edge_kernel<<<(E * 32 + 255) / 256, 256>>>(w, src, dst, E);
    agg_kernel<<<ew_grid, 256>>>();
    gemm_relu_stats<256, 1><<<gemm_grid, 256>>>(feat, Ww, Wb);
    bn_params<<<1, 128>>>(1, gamma, beta);
    final_kernel<<<ew_grid, 256>>>(out);
}

// round 4
// speedup vs baseline: 1.4921x; 1.4921x over previous
#include <cuda_runtime.h>
#include <math.h>

#define N_NODES 50000
#define D 128
#define EPS 1e-5f
#define E_MAX 800000

// -------- scratch (allocation-free: __device__ globals) --------
__device__ float g_h[N_NODES * D];      // raw relu(Q feat) (pre-BN)
__device__ float g_agg[N_NODES * D];    // final aggregated+BN'd features
__device__ float g_rst[N_NODES * D];    // relu(GEMM2) output
__device__ int   g_cnt[N_NODES];        // histogram -> scatter cursor
__device__ int   g_off[N_NODES + 1];    // CSR offsets
__device__ int   g_esrc[E_MAX];         // dst-sorted edge srcs
__device__ float g_ew[E_MAX];           // dst-sorted edge weights
__device__ float g_sum1[D], g_sq1[D], g_sum2[D], g_sq2[D];
__device__ float g_a1[D], g_b1[D], g_a2[D], g_b2[D];

// -------- zero per-replay accumulators (graph replay!) --------
__global__ void zero_kernel() {
    int idx = blockIdx.x * blockDim.x + threadIdx.x;
    int tot = blockDim.x * gridDim.x;
    for (int i = idx; i < N_NODES; i += tot) g_cnt[i] = 0;
    if (idx < D) { g_sum1[idx] = 0.f; g_sq1[idx] = 0.f; g_sum2[idx] = 0.f; g_sq2[idx] = 0.f; }
}

// -------- tiled SIMT fp32 GEMM: C = relu(A_concat @ B^T + bias), fused col stats --------
template <int K, int PHASE>
__global__ __launch_bounds__(256) void gemm_relu_stats(
    const float* __restrict__ A, const float* __restrict__ B,
    const float* __restrict__ bias)
{
    __shared__ float As[32][64];
    __shared__ float Bs[32][128];
    __shared__ float s_sum[128];
    __shared__ float s_sq[128];

    const int tid = threadIdx.x;
    const int r0 = blockIdx.x * 64;
    const int tcol = tid & 31;   // cols 4*tcol .. 4*tcol+3
    const int trow = tid >> 5;   // rows 8*trow .. 8*trow+7

    float acc[8][4];
#pragma unroll
    for (int r = 0; r < 8; r++)
#pragma unroll
        for (int c = 0; c < 4; c++) acc[r][c] = 0.f;

    for (int k0 = 0; k0 < K; k0 += 32) {
        const float* Asrc = (PHASE == 1 && k0 >= 128) ? g_agg : A;
        const int kbase = (PHASE == 1 && k0 >= 128) ? (k0 - 128) : k0;

        // A tile: 64 rows x 32 k -> As[k][row]
#pragma unroll
        for (int i = 0; i < 2; i++) {
            int idx = tid + i * 256;
            int row = idx & 63;
            int kk4 = (idx >> 6) << 2;
            int grow = r0 + row;
            float4 v = make_float4(0.f, 0.f, 0.f, 0.f);
            if (grow < N_NODES)
                v = *(const float4*)(Asrc + (size_t)grow * 128 + kbase + kk4);
            As[kk4 + 0][row] = v.x; As[kk4 + 1][row] = v.y;
            As[kk4 + 2][row] = v.z; As[kk4 + 3][row] = v.w;
        }
        // B tile: 128 j x 32 k -> Bs[k][j]
#pragma unroll
        for (int i = 0; i < 4; i++) {
            int idx = tid + i * 256;
            int j = idx & 127;
            int kk4 = (idx >> 7) << 2;
            float4 v = *(const float4*)(B + (size_t)j * K + k0 + kk4);
            Bs[kk4 + 0][j] = v.x; Bs[kk4 + 1][j] = v.y;
            Bs[kk4 + 2][j] = v.z; Bs[kk4 + 3][j] = v.w;
        }
        __syncthreads();

#pragma unroll
        for (int kk = 0; kk < 32; kk++) {
            float4 b4 = *(const float4*)&Bs[kk][tcol * 4];
            float4 a0 = *(const float4*)&As[kk][trow * 8];
            float4 a1 = *(const float4*)&As[kk][trow * 8 + 4];
            float ar[8] = {a0.x, a0.y, a0.z, a0.w, a1.x, a1.y, a1.z, a1.w};
            float bc[4] = {b4.x, b4.y, b4.z, b4.w};
#pragma unroll
            for (int r = 0; r < 8; r++)
#pragma unroll
                for (int c = 0; c < 4; c++) acc[r][c] += ar[r] * bc[c];
        }
        __syncthreads();
    }

    if (tid < 128) { s_sum[tid] = 0.f; s_sq[tid] = 0.f; }
    __syncthreads();

    float bsv[4];
#pragma unroll
    for (int c = 0; c < 4; c++) bsv[c] = bias[tcol * 4 + c];

    float* Cout = (PHASE == 0) ? g_h : g_rst;
    float ps[4] = {0.f, 0.f, 0.f, 0.f};
    float pq[4] = {0.f, 0.f, 0.f, 0.f};
#pragma unroll
    for (int r = 0; r < 8; r++) {
        int grow = r0 + trow * 8 + r;
        if (grow < N_NODES) {
            float4 v;
            float vv[4];
#pragma unroll
            for (int c = 0; c < 4; c++) {
                float x = acc[r][c] + bsv[c];
                x = fmaxf(x, 0.f);
                vv[c] = x;
                ps[c] += x;
                pq[c] += x * x;
            }
            v.x = vv[0]; v.y = vv[1]; v.z = vv[2]; v.w = vv[3];
            *(float4*)(Cout + (size_t)grow * 128 + tcol * 4) = v;
        }
    }
#pragma unroll
    for (int c = 0; c < 4; c++) {
        atomicAdd(&s_sum[tcol * 4 + c], ps[c]);
        atomicAdd(&s_sq[tcol * 4 + c], pq[c]);
    }
    __syncthreads();
    if (tid < 128) {
        float* gsum = (PHASE == 0) ? g_sum1 : g_sum2;
        float* gsq  = (PHASE == 0) ? g_sq1  : g_sq2;
        atomicAdd(&gsum[tid], s_sum[tid]);
        atomicAdd(&gsq[tid], s_sq[tid]);
    }
}

// -------- BN params: a = gamma*rstd, b = beta - mean*a --------
__global__ void bn_params(int phase, const float* __restrict__ gamma,
                          const float* __restrict__ beta) {
    int c = threadIdx.x;
    const float* sum = phase ? g_sum2 : g_sum1;
    const float* sq  = phase ? g_sq2  : g_sq1;
    float* pa = phase ? g_a2 : g_a1;
    float* pb = phase ? g_b2 : g_b1;
    float mean = sum[c] * (1.f / N_NODES);
    float var = sq[c] * (1.f / N_NODES) - mean * mean;
    float rstd = rsqrtf(var + EPS);
    float a = gamma[c] * rstd;
    pa[c] = a;
    pb[c] = beta[c] - mean * a;
}

// -------- CSR build: histogram of dst --------
__global__ void hist_kernel(const int* __restrict__ dst, int E) {
    int i = blockIdx.x * blockDim.x + threadIdx.x;
    if (i < E) atomicAdd(&g_cnt[dst[i]], 1);
}

// -------- single-block prefix scan: g_off[i+1]=incl, g_cnt[i]=excl (cursor) --------
__global__ __launch_bounds__(1024) void prefix_kernel() {
    __shared__ int wsum[32];
    __shared__ int carry;
    int tid = threadIdx.x, lane = tid & 31, wid = tid >> 5;
    if (tid == 0) { carry = 0; g_off[0] = 0; }
    __syncthreads();
    for (int base = 0; base < N_NODES; base += 1024) {
        int i = base + tid;
        int v = (i < N_NODES) ? g_cnt[i] : 0;
        int x = v;
#pragma unroll
        for (int o = 1; o < 32; o <<= 1) {
            int y = __shfl_up_sync(0xFFFFFFFFu, x, o);
            if (lane >= o) x += y;
        }
        if (lane == 31) wsum[wid] = x;
        __syncthreads();
        if (wid == 0) {
            int s = wsum[lane];
#pragma unroll
            for (int o = 1; o < 32; o <<= 1) {
                int y = __shfl_up_sync(0xFFFFFFFFu, s, o);
                if (lane >= o) s += y;
            }
            wsum[lane] = s;
        }
        __syncthreads();
        int wbase = (wid == 0) ? 0 : wsum[wid - 1];
        int incl = carry + wbase + x;
        if (i < N_NODES) {
            g_off[i + 1] = incl;
            g_cnt[i] = incl - v;  // exclusive prefix = scatter cursor start
        }
        __syncthreads();
        if (tid == 0) carry += wsum[31];
        __syncthreads();
    }
}

// -------- scatter edges into dst-sorted CSR order --------
__global__ void scatter_kernel(const float* __restrict__ w, const int* __restrict__ src,
                               const int* __restrict__ dst, int E) {
    int i = blockIdx.x * blockDim.x + threadIdx.x;
    if (i >= E) return;
    int d = dst[i];
    int pos = atomicAdd(&g_cnt[d], 1);
    g_esrc[pos] = src[i];
    g_ew[pos] = w[i];
}

// -------- gather + BN1 fold + agg: warp per dst node, NO float atomics --------
// num of BN'd h = a*num_raw + b*den  ->  agg = a*(num_raw/den)+b ; fallback a*h+b
__global__ void gather_kernel() {
    int gw = (blockIdx.x * blockDim.x + threadIdx.x) >> 5;
    int lane = threadIdx.x & 31;
    if (gw >= N_NODES) return;
    int beg = g_off[gw], end = g_off[gw + 1];
    float4 acc = make_float4(0.f, 0.f, 0.f, 0.f);
    float den = 0.f;
    for (int j = beg; j < end; j++) {
        int s = g_esrc[j];          // warp-uniform broadcast load
        float we = g_ew[j];
        float4 hv = ((const float4*)g_h)[(size_t)s * 32 + lane];
        acc.x += we * hv.x; acc.y += we * hv.y;
        acc.z += we * hv.z; acc.w += we * hv.w;
        den += we;
    }
    float4 a = ((const float4*)g_a1)[lane];
    float4 b = ((const float4*)g_b1)[lane];
    float4 v;
    if (den != 0.f) {
        float inv = 1.f / den;
        v.x = a.x * (acc.x * inv) + b.x;
        v.y = a.y * (acc.y * inv) + b.y;
        v.z = a.z * (acc.z * inv) + b.z;
        v.w = a.w * (acc.w * inv) + b.w;
    } else {
        float4 hv = ((const float4*)g_h)[(size_t)gw * 32 + lane];
        v.x = a.x * hv.x + b.x;
        v.y = a.y * hv.y + b.y;
        v.z = a.z * hv.z + b.z;
        v.w = a.w * hv.w + b.w;
    }
    ((float4*)g_agg)[(size_t)gw * 32 + lane] = v;
}

// -------- BN2 + row L2 normalize: warp per row --------
__global__ void final_kernel(float* __restrict__ out) {
    int gw = (blockIdx.x * blockDim.x + threadIdx.x) >> 5;
    int lane = threadIdx.x & 31;
    if (gw >= N_NODES) return;
    float4 a = ((const float4*)g_a2)[lane];
    float4 b = ((const float4*)g_b2)[lane];
    float4 v = ((const float4*)g_rst)[(size_t)gw * 32 + lane];
    v.x = v.x * a.x + b.x; v.y = v.y * a.y + b.y;
    v.z = v.z * a.z + b.z; v.w = v.w * a.w + b.w;
    float ss = v.x * v.x + v.y * v.y + v.z * v.z + v.w * v.w;
#pragma unroll
    for (int o = 16; o > 0; o >>= 1) ss += __shfl_xor_sync(0xFFFFFFFFu, ss, o);
    float norm = sqrtf(ss);
    float inv = (norm == 0.f) ? 1.f : 1.f / norm;
    v.x *= inv; v.y *= inv; v.z *= inv; v.w *= inv;
    ((float4*)out)[(size_t)gw * 32 + lane] = v;
}

extern "C" void kernel_launch(void* const* d_in, const int* in_sizes, int n_in,
                              void* d_out, int out_size) {
    const float* feat  = (const float*)d_in[0];
    const float* w     = (const float*)d_in[1];
    const float* Qw    = (const float*)d_in[2];
    const float* Qb    = (const float*)d_in[3];
    const float* Ww    = (const float*)d_in[4];
    const float* Wb    = (const float*)d_in[5];
    const float* gamma = (const float*)d_in[6];
    const float* beta  = (const float*)d_in[7];
    const int* src     = (const int*)d_in[8];
    const int* dst     = (const int*)d_in[9];
    const int E = in_sizes[1];
    float* out = (float*)d_out;

    const int gemm_grid = (N_NODES + 63) / 64;          // 782
    const int warp_grid = (N_NODES * 32 + 255) / 256;   // 6250
    const int e_grid = (E + 255) / 256;

    zero_kernel<<<128, 256>>>();
    hist_kernel<<<e_grid, 256>>>(dst, E);
    prefix_kernel<<<1, 1024>>>();
    scatter_kernel<<<e_grid, 256>>>(w, src, dst, E);
    gemm_relu_stats<128, 0><<<gemm_grid, 256>>>(feat, Qw, Qb);
    bn_params<<<1, 128>>>(0, gamma, beta);
    gather_kernel<<<warp_grid, 256>>>();
    gemm_relu_stats<256, 1><<<gemm_grid, 256>>>(feat, Ww, Wb);
    bn_params<<<1, 128>>>(1, gamma, beta);
    final_kernel<<<warp_grid, 256>>>(out);
}

// round 7
// speedup vs baseline: 2.0422x; 1.3686x over previous
#include <cuda_runtime.h>
#include <cuda_bf16.h>
#include <math.h>
#include <stdint.h>

#define N_NODES 50000
#define D 128
#define EPS 1e-5f
#define E_MAX 800000

// padded bf16 tile: 128 rows x 64 cols, row stride 72 elems (144B = 9*16B -> bank rotate)
#define TROW 144
#define TILE_BYTES (128 * TROW)   // 18432

// ================= scratch (allocation-free: __device__ globals) =================
__device__ float g_h[N_NODES * D];
__device__ float g_agg[N_NODES * D];
__device__ float g_rst[N_NODES * D];
__device__ int   g_cnt[N_NODES];
__device__ int   g_off[N_NODES + 1];
__device__ int   g_esrc[E_MAX];
__device__ float g_ew[E_MAX];
__device__ float g_sum1[D], g_sq1[D], g_sum2[D], g_sq2[D];
__device__ float g_a1[D], g_b1[D], g_a2[D], g_b2[D];
// pre-split B images in padded tile layout: [chunk][hi/lo][TILE_BYTES]
__device__ unsigned char g_B1img[2][2][TILE_BYTES];
__device__ unsigned char g_B2img[4][2][TILE_BYTES];

// ================= warp-mma helpers (sm_80 baseline, legal in compute_103) =================
__device__ __forceinline__ uint32_t smem_u32(const void* p) {
    uint32_t a;
    asm("{ .reg .u64 t; cvta.to.shared.u64 t, %1; cvt.u32.u64 %0, t; }" : "=r"(a) : "l"(p));
    return a;
}
__device__ __forceinline__ void ldsm_x4(uint32_t* r, uint32_t addr) {
    asm volatile("ldmatrix.sync.aligned.m8n8.x4.shared.b16 {%0,%1,%2,%3}, [%4];"
                 : "=r"(r[0]), "=r"(r[1]), "=r"(r[2]), "=r"(r[3]) : "r"(addr));
}
__device__ __forceinline__ void mma_bf16(float* d, const uint32_t* a, const uint32_t* b) {
    asm volatile(
        "mma.sync.aligned.m16n8k16.row.col.f32.bf16.bf16.f32 "
        "{%0,%1,%2,%3}, {%4,%5,%6,%7}, {%8,%9}, {%0,%1,%2,%3};"
        : "+f"(d[0]), "+f"(d[1]), "+f"(d[2]), "+f"(d[3])
        : "r"(a[0]), "r"(a[1]), "r"(a[2]), "r"(a[3]), "r"(b[0]), "r"(b[1]));
}

// ================= zero per-replay accumulators =================
__global__ void zero_kernel() {
    int idx = blockIdx.x * blockDim.x + threadIdx.x;
    int tot = blockDim.x * gridDim.x;
    for (int i = idx; i < N_NODES; i += tot) g_cnt[i] = 0;
    if (idx < D) { g_sum1[idx] = 0.f; g_sq1[idx] = 0.f; g_sum2[idx] = 0.f; g_sq2[idx] = 0.f; }
}

// ================= weight prep: split fp32 -> (bf16 hi, bf16 lo), padded layout =================
__global__ void prep_B(const float* __restrict__ Qw, const float* __restrict__ Ww) {
    int idx = blockIdx.x * blockDim.x + threadIdx.x;
    if (idx < 16384) {                       // Qw: 128 x 128
        int r = idx >> 7, k = idx & 127;
        int chunk = k >> 6, kk = k & 63;
        float x = Qw[r * 128 + k];
        __nv_bfloat16 hi = __float2bfloat16_rn(x);
        __nv_bfloat16 lo = __float2bfloat16_rn(x - __bfloat162float(hi));
        uint32_t off = (uint32_t)(r * TROW + kk * 2);
        *(__nv_bfloat16*)(&g_B1img[chunk][0][off]) = hi;
        *(__nv_bfloat16*)(&g_B1img[chunk][1][off]) = lo;
    } else if (idx < 16384 + 32768) {        // Ww: 128 x 256
        int e = idx - 16384;
        int r = e >> 8, k = e & 255;
        int chunk = k >> 6, kk = k & 63;
        float x = Ww[r * 256 + k];
        __nv_bfloat16 hi = __float2bfloat16_rn(x);
        __nv_bfloat16 lo = __float2bfloat16_rn(x - __bfloat162float(hi));
        uint32_t off = (uint32_t)(r * TROW + kk * 2);
        *(__nv_bfloat16*)(&g_B2img[chunk][0][off]) = hi;
        *(__nv_bfloat16*)(&g_B2img[chunk][1][off]) = lo;
    }
}

// ================= HMMA GEMM: C = relu(A_concat @ B^T + bias) =================
// CTA: 128 rows x 128 cols. 8 warps, each 32x64 (warp_m=wid&3 -> rows, warp_n=wid>>2 -> cols).
// K chunks of 64; split-bf16 3-pass accumulate (AhBh + AhBl + AlBh).
#define SM_BIAS 0
#define SM_AHI  1024
#define SM_ALO  (1024 + TILE_BYTES)
#define SM_BHI  (1024 + 2 * TILE_BYTES)
#define SM_BLO  (1024 + 3 * TILE_BYTES)
#define SM_TOTAL (1024 + 4 * TILE_BYTES)   // 74752

template <int PHASE>
__global__ __launch_bounds__(256) void hmma_gemm(const float* __restrict__ A,
                                                 const float* __restrict__ bias) {
    extern __shared__ char smem[];
    const uint32_t sbase = smem_u32(smem);
    const int tid = threadIdx.x;
    const int wid = tid >> 5;
    const int lane = tid & 31;
    const int r0 = blockIdx.x * 128;
    const int NC = (PHASE == 0) ? 2 : 4;

    if (tid < 128) *(float*)(smem + SM_BIAS + tid * 4) = bias[tid];

    // A-fill mapping: 2 threads per row, 32 cols each
    const int frow = tid >> 1;
    const int fhalf = tid & 1;
    const bool fvalid = (r0 + frow < N_NODES);

    // ldmatrix address components
    const int warp_m = wid & 3;
    const int warp_n = wid >> 2;
    const uint32_t a_off = (uint32_t)((warp_m * 32 + (lane & 15)) * TROW + (lane >> 4) * 16);
    const uint32_t b_off = (uint32_t)((warp_n * 64 + (lane & 7) + ((lane >> 4) << 3)) * TROW
                                      + ((lane >> 3) & 1) * 16);

    float acc[2][8][4];
#pragma unroll
    for (int mt = 0; mt < 2; mt++)
#pragma unroll
        for (int nt = 0; nt < 8; nt++)
#pragma unroll
            for (int q = 0; q < 4; q++) acc[mt][nt][q] = 0.f;

    for (int c = 0; c < NC; c++) {
        // ---- fill A tile (128 x 64) split hi/lo ----
        const float* Asrc;
        int kbase;
        if (PHASE == 0) { Asrc = A; kbase = c * 64; }
        else if (c < 2) { Asrc = A; kbase = c * 64; }
        else            { Asrc = g_agg; kbase = (c - 2) * 64; }

        const float* rp = Asrc + (size_t)(fvalid ? (r0 + frow) : 0) * 128 + kbase + fhalf * 32;
#pragma unroll
        for (int i = 0; i < 8; i++) {
            float4 v = fvalid ? *(const float4*)(rp + i * 4) : make_float4(0.f, 0.f, 0.f, 0.f);
            __nv_bfloat162 h01, h23, l01, l23;
            h01.x = __float2bfloat16_rn(v.x); h01.y = __float2bfloat16_rn(v.y);
            h23.x = __float2bfloat16_rn(v.z); h23.y = __float2bfloat16_rn(v.w);
            l01.x = __float2bfloat16_rn(v.x - __bfloat162float(h01.x));
            l01.y = __float2bfloat16_rn(v.y - __bfloat162float(h01.y));
            l23.x = __float2bfloat16_rn(v.z - __bfloat162float(h23.x));
            l23.y = __float2bfloat16_rn(v.w - __bfloat162float(h23.y));
            uint32_t off = (uint32_t)(frow * TROW + (fhalf * 32 + i * 4) * 2);
            *(__nv_bfloat162*)(smem + SM_AHI + off) = h01;
            *(__nv_bfloat162*)(smem + SM_AHI + off + 4) = h23;
            *(__nv_bfloat162*)(smem + SM_ALO + off) = l01;
            *(__nv_bfloat162*)(smem + SM_ALO + off + 4) = l23;
        }
        // ---- copy pre-split B images ----
        {
            const float4* bh = (PHASE == 0) ? (const float4*)g_B1img[c][0] : (const float4*)g_B2img[c][0];
            const float4* bl = (PHASE == 0) ? (const float4*)g_B1img[c][1] : (const float4*)g_B2img[c][1];
            float4* dh = (float4*)(smem + SM_BHI);
            float4* dl = (float4*)(smem + SM_BLO);
            const int nf4 = TILE_BYTES / 16;   // 1152
            for (int j = tid; j < nf4; j += 256) {
                dh[j] = bh[j];
                dl[j] = bl[j];
            }
        }
        __syncthreads();

        // ---- 4 K-steps of m16n8k16 ----
#pragma unroll
        for (int ks = 0; ks < 4; ks++) {
            uint32_t ah[2][4], al[2][4];
#pragma unroll
            for (int mt = 0; mt < 2; mt++) {
                uint32_t o = a_off + mt * (16 * TROW) + ks * 32;
                ldsm_x4(ah[mt], sbase + SM_AHI + o);
                ldsm_x4(al[mt], sbase + SM_ALO + o);
            }
            uint32_t bh[4][4], bl[4][4];
#pragma unroll
            for (int ng = 0; ng < 4; ng++) {
                uint32_t o = b_off + ng * (16 * TROW) + ks * 32;
                ldsm_x4(bh[ng], sbase + SM_BHI + o);
                ldsm_x4(bl[ng], sbase + SM_BLO + o);
            }
#pragma unroll
            for (int mt = 0; mt < 2; mt++)
#pragma unroll
                for (int ng = 0; ng < 4; ng++) {
                    mma_bf16(acc[mt][ng * 2 + 0], ah[mt], &bh[ng][0]);
                    mma_bf16(acc[mt][ng * 2 + 1], ah[mt], &bh[ng][2]);
                    mma_bf16(acc[mt][ng * 2 + 0], ah[mt], &bl[ng][0]);
                    mma_bf16(acc[mt][ng * 2 + 1], ah[mt], &bl[ng][2]);
                    mma_bf16(acc[mt][ng * 2 + 0], al[mt], &bh[ng][0]);
                    mma_bf16(acc[mt][ng * 2 + 1], al[mt], &bh[ng][2]);
                }
        }
        __syncthreads();
    }

    // ---- epilogue: bias + relu + store ----
    float* Cout = (PHASE == 0) ? g_h : g_rst;
    const int er = r0 + warp_m * 32 + (lane >> 2);
    const int ec = warp_n * 64 + (lane & 3) * 2;
#pragma unroll
    for (int mt = 0; mt < 2; mt++) {
#pragma unroll
        for (int nt = 0; nt < 8; nt++) {
            int col = ec + nt * 8;
            float bx = *(float*)(smem + SM_BIAS + col * 4);
            float by = *(float*)(smem + SM_BIAS + (col + 1) * 4);
            int row = er + mt * 16;
            if (row < N_NODES) {
                float2 v;
                v.x = fmaxf(acc[mt][nt][0] + bx, 0.f);
                v.y = fmaxf(acc[mt][nt][1] + by, 0.f);
                *(float2*)(Cout + (size_t)row * 128 + col) = v;
            }
            if (row + 8 < N_NODES) {
                float2 v;
                v.x = fmaxf(acc[mt][nt][2] + bx, 0.f);
                v.y = fmaxf(acc[mt][nt][3] + by, 0.f);
                *(float2*)(Cout + (size_t)(row + 8) * 128 + col) = v;
            }
        }
    }
}

// ================= column stats: sum & sumsq over rows =================
template <int PHASE>
__global__ void stats_kernel() {
    __shared__ float s_s[128], s_q[128];
    const float* X = (PHASE == 0) ? g_h : g_rst;
    int tid = threadIdx.x;
    if (tid < 128) { s_s[tid] = 0.f; s_q[tid] = 0.f; }
    __syncthreads();
    int lane = tid & 31;
    int wg = (blockIdx.x * blockDim.x + tid) >> 5;
    int wt = (gridDim.x * blockDim.x) >> 5;
    float4 s = make_float4(0.f, 0.f, 0.f, 0.f);
    float4 q = make_float4(0.f, 0.f, 0.f, 0.f);
    for (int r = wg; r < N_NODES; r += wt) {
        float4 v = ((const float4*)X)[(size_t)r * 32 + lane];
        s.x += v.x; s.y += v.y; s.z += v.z; s.w += v.w;
        q.x += v.x * v.x; q.y += v.y * v.y; q.z += v.z * v.z; q.w += v.w * v.w;
    }
    atomicAdd(&s_s[lane * 4 + 0], s.x); atomicAdd(&s_s[lane * 4 + 1], s.y);
    atomicAdd(&s_s[lane * 4 + 2], s.z); atomicAdd(&s_s[lane * 4 + 3], s.w);
    atomicAdd(&s_q[lane * 4 + 0], q.x); atomicAdd(&s_q[lane * 4 + 1], q.y);
    atomicAdd(&s_q[lane * 4 + 2], q.z); atomicAdd(&s_q[lane * 4 + 3], q.w);
    __syncthreads();
    if (tid < 128) {
        float* gs = (PHASE == 0) ? g_sum1 : g_sum2;
        float* gq = (PHASE == 0) ? g_sq1 : g_sq2;
        atomicAdd(&gs[tid], s_s[tid]);
        atomicAdd(&gq[tid], s_q[tid]);
    }
}

// ================= BN params =================
__global__ void bn_params(int phase, const float* __restrict__ gamma,
                          const float* __restrict__ beta) {
    int c = threadIdx.x;
    const float* sum = phase ? g_sum2 : g_sum1;
    const float* sq  = phase ? g_sq2  : g_sq1;
    float* pa = phase ? g_a2 : g_a1;
    float* pb = phase ? g_b2 : g_b1;
    float mean = sum[c] * (1.f / N_NODES);
    float var = sq[c] * (1.f / N_NODES) - mean * mean;
    float rstd = rsqrtf(var + EPS);
    float a = gamma[c] * rstd;
    pa[c] = a;
    pb[c] = beta[c] - mean * a;
}

// ================= CSR build =================
__global__ void hist_kernel(const int* __restrict__ dst, int E) {
    int i = blockIdx.x * blockDim.x + threadIdx.x;
    if (i < E) atomicAdd(&g_cnt[dst[i]], 1);
}

__global__ __launch_bounds__(1024) void prefix_kernel() {
    __shared__ int wsum[32];
    __shared__ int carry;
    int tid = threadIdx.x, lane = tid & 31, wid = tid >> 5;
    if (tid == 0) { carry = 0; g_off[0] = 0; }
    __syncthreads();
    for (int base = 0; base < N_NODES; base += 1024) {
        int i = base + tid;
        int v = (i < N_NODES) ? g_cnt[i] : 0;
        int x = v;
#pragma unroll
        for (int o = 1; o < 32; o <<= 1) {
            int y = __shfl_up_sync(0xFFFFFFFFu, x, o);
            if (lane >= o) x += y;
        }
        if (lane == 31) wsum[wid] = x;
        __syncthreads();
        if (wid == 0) {
            int s = wsum[lane];
#pragma unroll
            for (int o = 1; o < 32; o <<= 1) {
                int y = __shfl_up_sync(0xFFFFFFFFu, s, o);
                if (lane >= o) s += y;
            }
            wsum[lane] = s;
        }
        __syncthreads();
        int wbase = (wid == 0) ? 0 : wsum[wid - 1];
        int incl = carry + wbase + x;
        if (i < N_NODES) {
            g_off[i + 1] = incl;
            g_cnt[i] = incl - v;
        }
        __syncthreads();
        if (tid == 0) carry += wsum[31];
        __syncthreads();
    }
}

__global__ void scatter_kernel(const float* __restrict__ w, const int* __restrict__ src,
                               const int* __restrict__ dst, int E) {
    int i = blockIdx.x * blockDim.x + threadIdx.x;
    if (i >= E) return;
    int d = dst[i];
    int pos = atomicAdd(&g_cnt[d], 1);
    g_esrc[pos] = src[i];
    g_ew[pos] = w[i];
}

// ================= gather + BN1 fold: warp per dst node =================
__global__ void gather_kernel() {
    int gw = (blockIdx.x * blockDim.x + threadIdx.x) >> 5;
    int lane = threadIdx.x & 31;
    if (gw >= N_NODES) return;
    int beg = g_off[gw], end = g_off[gw + 1];
    float4 acc = make_float4(0.f, 0.f, 0.f, 0.f);
    float den = 0.f;
    for (int j = beg; j < end; j++) {
        int s = g_esrc[j];
        float we = g_ew[j];
        float4 hv = ((const float4*)g_h)[(size_t)s * 32 + lane];
        acc.x += we * hv.x; acc.y += we * hv.y;
        acc.z += we * hv.z; acc.w += we * hv.w;
        den += we;
    }
    float4 a = ((const float4*)g_a1)[lane];
    float4 b = ((const float4*)g_b1)[lane];
    float4 v;
    if (den != 0.f) {
        float inv = 1.f / den;
        v.x = a.x * (acc.x * inv) + b.x;
        v.y = a.y * (acc.y * inv) + b.y;
        v.z = a.z * (acc.z * inv) + b.z;
        v.w = a.w * (acc.w * inv) + b.w;
    } else {
        float4 hv = ((const float4*)g_h)[(size_t)gw * 32 + lane];
        v.x = a.x * hv.x + b.x;
        v.y = a.y * hv.y + b.y;
        v.z = a.z * hv.z + b.z;
        v.w = a.w * hv.w + b.w;
    }
    ((float4*)g_agg)[(size_t)gw * 32 + lane] = v;
}

// ================= BN2 + L2 normalize =================
__global__ void final_kernel(float* __restrict__ out) {
    int gw = (blockIdx.x * blockDim.x + threadIdx.x) >> 5;
    int lane = threadIdx.x & 31;
    if (gw >= N_NODES) return;
    float4 a = ((const float4*)g_a2)[lane];
    float4 b = ((const float4*)g_b2)[lane];
    float4 v = ((const float4*)g_rst)[(size_t)gw * 32 + lane];
    v.x = v.x * a.x + b.x; v.y = v.y * a.y + b.y;
    v.z = v.z * a.z + b.z; v.w = v.w * a.w + b.w;
    float ss = v.x * v.x + v.y * v.y + v.z * v.z + v.w * v.w;
#pragma unroll
    for (int o = 16; o > 0; o >>= 1) ss += __shfl_xor_sync(0xFFFFFFFFu, ss, o);
    float norm = sqrtf(ss);
    float inv = (norm == 0.f) ? 1.f : 1.f / norm;
    v.x *= inv; v.y *= inv; v.z *= inv; v.w *= inv;
    ((float4*)out)[(size_t)gw * 32 + lane] = v;
}

extern "C" void kernel_launch(void* const* d_in, const int* in_sizes, int n_in,
                              void* d_out, int out_size) {
    const float* feat  = (const float*)d_in[0];
    const float* w     = (const float*)d_in[1];
    const float* Qw    = (const float*)d_in[2];
    const float* Qb    = (const float*)d_in[3];
    const float* Ww    = (const float*)d_in[4];
    const float* Wb    = (const float*)d_in[5];
    const float* gamma = (const float*)d_in[6];
    const float* beta  = (const float*)d_in[7];
    const int* src     = (const int*)d_in[8];
    const int* dst     = (const int*)d_in[9];
    const int E = in_sizes[1];
    float* out = (float*)d_out;

    static int smem_set = 0;
    if (!smem_set) {
        cudaFuncSetAttribute(hmma_gemm<0>, cudaFuncAttributeMaxDynamicSharedMemorySize, SM_TOTAL);
        cudaFuncSetAttribute(hmma_gemm<1>, cudaFuncAttributeMaxDynamicSharedMemorySize, SM_TOTAL);
        smem_set = 1;
    }

    const int tile_grid = (N_NODES + 127) / 128;        // 391
    const int warp_grid = (N_NODES * 32 + 255) / 256;   // 6250
    const int e_grid = (E + 255) / 256;

    zero_kernel<<<128, 256>>>();
    hist_kernel<<<e_grid, 256>>>(dst, E);
    prefix_kernel<<<1, 1024>>>();
    scatter_kernel<<<e_grid, 256>>>(w, src, dst, E);
    prep_B<<<192, 256>>>(Qw, Ww);
    hmma_gemm<0><<<tile_grid, 256, SM_TOTAL>>>(feat, Qb);
    stats_kernel<0><<<128, 256>>>();
    bn_params<<<1, 128>>>(0, gamma, beta);
    gather_kernel<<<warp_grid, 256>>>();
    hmma_gemm<1><<<tile_grid, 256, SM_TOTAL>>>(feat, Wb);
    stats_kernel<1><<<128, 256>>>();
    bn_params<<<1, 128>>>(1, gamma, beta);
    final_kernel<<<warp_grid, 256>>>(out);
}